// round 17
// baseline (speedup 1.0000x reference)
#include <cuda_runtime.h>
#include <cuda_fp16.h>
#include <cstdint>
#include <cstddef>

#define IN_DIM   1024
#define HID_DIM  512
#define OUT_DIM  1024
#define N_EXP    6
#define H3       3072
#define MAXB     32768

// ---------------- scratch (device globals; no allocation allowed) ----------
__device__ float  g_gate[(size_t)MAXB * N_EXP];
__device__ __half g_xh [(size_t)MAXB * IN_DIM];    // fp16(x)
__device__ __half g_w1 [(size_t)H3 * IN_DIM];      // fp16(W1^T) [3072,1024] K contig
__device__ __half g_w2 [(size_t)OUT_DIM * H3];     // fp16(W2^T) [1024,3072] K contig
__device__ __half g_hs [(size_t)MAXB * H3];        // fp16 hidden

// ---------------- helpers ---------------------------------------------------
__device__ __forceinline__ uint32_t smem_u32(const void* p) {
    uint32_t a;
    asm("{ .reg .u64 t; cvta.to.shared.u64 t, %1; cvt.u32.u64 %0, t; }" : "=r"(a) : "l"(p));
    return a;
}
__device__ __forceinline__ void cp16(uint32_t dst, const void* src) {
    asm volatile("cp.async.cg.shared.global [%0], [%1], 16;" :: "r"(dst), "l"(src));
}
__device__ __forceinline__ void cp_commit() {
    asm volatile("cp.async.commit_group;" ::: "memory");
}
template <int N>
__device__ __forceinline__ void cp_wait() {
    asm volatile("cp.async.wait_group %0;" :: "n"(N) : "memory");
}
__device__ __forceinline__ void ldsm4(uint32_t* r, uint32_t addr) {
    asm volatile("ldmatrix.sync.aligned.m8n8.x4.shared.b16 {%0,%1,%2,%3}, [%4];"
                 : "=r"(r[0]), "=r"(r[1]), "=r"(r[2]), "=r"(r[3]) : "r"(addr));
}
__device__ __forceinline__ void mma_f16(float* c, const uint32_t* a, const uint32_t* b) {
    asm volatile(
        "mma.sync.aligned.m16n8k16.row.col.f32.f16.f16.f32 "
        "{%0,%1,%2,%3}, {%4,%5,%6,%7}, {%8,%9}, {%0,%1,%2,%3};"
        : "+f"(c[0]), "+f"(c[1]), "+f"(c[2]), "+f"(c[3])
        : "r"(a[0]), "r"(a[1]), "r"(a[2]), "r"(a[3]), "r"(b[0]), "r"(b[1]));
}
// 64B rows, 16B chunks, xor-swizzle (conflict-free ldmatrix)
__device__ __forceinline__ int sw_off(int row, int chunk) {
    return row * 64 + ((chunk ^ ((row >> 1) & 3)) << 4);
}
__device__ __forceinline__ uint32_t pk_h2(float v0, float v1) {
    __half2 h = __halves2half2(__float2half_rn(v0), __float2half_rn(v1));
    return *reinterpret_cast<uint32_t*>(&h);
}

// ---------------- fused gate + fp16 quantize of x ---------------------------
__global__ __launch_bounds__(256) void gate_split_kernel(
    const float* __restrict__ x,
    const float* __restrict__ g2w, const float* __restrict__ g2b,
    const float* __restrict__ g3w, const float* __restrict__ g3b,
    float* __restrict__ gate, __half* __restrict__ xh, int B)
{
    int row  = (blockIdx.x * 256 + threadIdx.x) >> 5;
    int lane = threadIdx.x & 31;
    if (row >= B) return;

    const float4* xr = reinterpret_cast<const float4*>(x + (size_t)row * IN_DIM);
    float a0 = 0.f, a1 = 0.f, a2 = 0.f, a3 = 0.f;
    #pragma unroll
    for (int j = 0; j < 8; ++j) {
        int i = lane + j * 32;
        float4 v = xr[i];
        int k = i * 4;
        a0 = fmaf(v.x, g2w[k], fmaf(v.y, g2w[k+1], fmaf(v.z, g2w[k+2], fmaf(v.w, g2w[k+3], a0))));
        a1 = fmaf(v.x, g3w[k*3+0], fmaf(v.y, g3w[(k+1)*3+0], fmaf(v.z, g3w[(k+2)*3+0], fmaf(v.w, g3w[(k+3)*3+0], a1))));
        a2 = fmaf(v.x, g3w[k*3+1], fmaf(v.y, g3w[(k+1)*3+1], fmaf(v.z, g3w[(k+2)*3+1], fmaf(v.w, g3w[(k+3)*3+1], a2))));
        a3 = fmaf(v.x, g3w[k*3+2], fmaf(v.y, g3w[(k+1)*3+2], fmaf(v.z, g3w[(k+2)*3+2], fmaf(v.w, g3w[(k+3)*3+2], a3))));
        *reinterpret_cast<uint2*>(xh + (size_t)row * IN_DIM + k) =
            make_uint2(pk_h2(v.x, v.y), pk_h2(v.z, v.w));
    }
    #pragma unroll
    for (int off = 16; off > 0; off >>= 1) {
        a0 += __shfl_down_sync(0xffffffffu, a0, off);
        a1 += __shfl_down_sync(0xffffffffu, a1, off);
        a2 += __shfl_down_sync(0xffffffffu, a2, off);
        a3 += __shfl_down_sync(0xffffffffu, a3, off);
    }
    if (lane == 0) {
        float alpha = 1.f / (1.f + expf(-(a0 + g2b[0])));
        float l0 = a1 + g3b[0], l1 = a2 + g3b[1], l2 = a3 + g3b[2];
        float m = fmaxf(l0, fmaxf(l1, l2));
        float e0 = expf(l0 - m), e1 = expf(l1 - m), e2 = expf(l2 - m);
        float inv = 1.f / (e0 + e1 + e2);
        float p0 = e0 * inv, p1 = e1 * inv, p2 = e2 * inv, ga = 1.f - alpha;
        float* o = gate + (size_t)row * N_EXP;
        o[0] = ga * p0;    o[1] = ga * p1;    o[2] = ga * p2;
        o[3] = alpha * p0; o[4] = alpha * p1; o[5] = alpha * p2;
    }
}

// -------- transpose + quantize: src[R,C] fp32 -> dst[C,R] fp16 --------------
__global__ void transquant_kernel(const float* __restrict__ src,
                                  __half* __restrict__ dst, int R, int C)
{
    __shared__ float t[32][33];
    size_t zoff = (size_t)blockIdx.z * R * C;
    int c0 = blockIdx.x * 32, r0 = blockIdx.y * 32;
    int tx = threadIdx.x, ty = threadIdx.y;          // 32 x 8
    #pragma unroll
    for (int i = 0; i < 4; ++i)
        t[ty + i*8][tx] = src[zoff + (size_t)(r0 + ty + i*8) * C + c0 + tx];
    __syncthreads();
    #pragma unroll
    for (int i = 0; i < 4; ++i) {
        int c = c0 + ty + i*8, r = r0 + tx;
        dst[zoff + (size_t)c * R + r] = __float2half_rn(t[tx][ty + i*8]);
    }
}

// ======= GEMM1 (R15 config): CTA 128x128, 4 warps, warp 64x64, BK=64 ========
// 128 threads, 3-stage pipeline (32KB/stage = A 16K | B 16K; 96KB/CTA,
// 2 CTAs/SM). Measured best for K=1024.
#define G1_BM 128
#define G1_BN 128
#define G1_BK 64
#define G1_STAGES 3
#define G1_STAGE_BYTES 32768
#define G1_SMEM (G1_STAGES * G1_STAGE_BYTES)

template <int K>
__device__ __forceinline__ void g1_load_stage(
    uint32_t sb, const __half* __restrict__ Asrc,
    const __half* __restrict__ Bsrc, int k0, int tid)
{
    #pragma unroll
    for (int j = 0; j < 8; ++j) {            // A: 1024 chunks
        int idx = tid + j * 128;
        int sub = idx >> 9, ii = idx & 511;
        int row = ii >> 2, c = ii & 3;
        cp16(sb + sub * 8192 + sw_off(row, c),
             Asrc + (size_t)row * K + k0 + sub * 32 + c * 8);
    }
    #pragma unroll
    for (int j = 0; j < 8; ++j) {            // B: 1024 chunks
        int idx = tid + j * 128;
        int sub = idx >> 9, ii = idx & 511;
        int row = ii >> 2, c = ii & 3;
        cp16(sb + 16384 + sub * 8192 + sw_off(row, c),
             Bsrc + (size_t)row * K + k0 + c * 8 + sub * 32);
    }
    cp_commit();
}

__global__ __launch_bounds__(128, 2) void gemm1_mma(
    const __half* __restrict__ A, const __half* __restrict__ Bw,
    const float* __restrict__ bias, const float* __restrict__ gate,
    __half* __restrict__ Chs)
{
    extern __shared__ char smem[];
    const uint32_t sbase = smem_u32(smem);
    const int tid  = threadIdx.x;
    const int wid  = tid >> 5;
    const int lane = tid & 31;
    const int mBlk = blockIdx.y * G1_BM;
    const int nBlk = blockIdx.x * G1_BN;
    const int wm = (wid >> 1) * 64;
    const int wn = (wid & 1) * 64;
    constexpr int K = IN_DIM;
    constexpr int NK = K / G1_BK;

    const __half* Asrc = A  + (size_t)mBlk * K;
    const __half* Bsrc = Bw + (size_t)nBlk * K;

    float acc[4][8][4];
    #pragma unroll
    for (int i = 0; i < 4; ++i)
        #pragma unroll
        for (int j = 0; j < 8; ++j)
            #pragma unroll
            for (int q = 0; q < 4; ++q) acc[i][j][q] = 0.f;

    g1_load_stage<K>(sbase,                      Asrc, Bsrc, 0 * G1_BK, tid);
    g1_load_stage<K>(sbase + G1_STAGE_BYTES,     Asrc, Bsrc, 1 * G1_BK, tid);

    const int rA = wm + (lane & 15);
    const int rB = wn + ((lane >> 4) << 3) + (lane & 7);
    const int cAoff = lane >> 4;
    const int cBoff = (lane >> 3) & 1;

    #pragma unroll 3
    for (int s = 0; s < NK; ++s) {
        cp_wait<G1_STAGES - 2>();
        __syncthreads();
        const uint32_t sb = sbase + (s % G1_STAGES) * G1_STAGE_BYTES;

        if (s + G1_STAGES - 1 < NK)
            g1_load_stage<K>(sbase + ((s + G1_STAGES - 1) % G1_STAGES) * G1_STAGE_BYTES,
                             Asrc, Bsrc, (s + G1_STAGES - 1) * G1_BK, tid);
        else cp_commit();

        #pragma unroll
        for (int kk = 0; kk < 4; ++kk) {
            uint32_t Af[16], Bf[16];
            {
                const uint32_t baseA = sb + (kk >> 1) * 8192;
                const int ca = (kk & 1) * 2 + cAoff;
                #pragma unroll
                for (int mi = 0; mi < 4; ++mi)
                    ldsm4(Af + mi * 4, baseA + sw_off(rA + 16 * mi, ca));
            }
            {
                const uint32_t baseB = sb + 16384 + (kk >> 1) * 8192;
                const int cb = (kk & 1) * 2 + cBoff;
                #pragma unroll
                for (int jp = 0; jp < 4; ++jp) {
                    uint32_t t[4];
                    ldsm4(t, baseB + sw_off(rB + 16 * jp, cb));
                    Bf[(2 * jp) * 2]         = t[0];
                    Bf[(2 * jp) * 2 + 1]     = t[1];
                    Bf[(2 * jp + 1) * 2]     = t[2];
                    Bf[(2 * jp + 1) * 2 + 1] = t[3];
                }
            }
            #pragma unroll
            for (int mi = 0; mi < 4; ++mi)
                #pragma unroll
                for (int nj = 0; nj < 8; ++nj)
                    mma_f16(acc[mi][nj], Af + mi * 4, Bf + nj * 2);
        }
    }

    // epilogue: hs = fp16(relu(acc + b1) * gate)
    const int e = nBlk >> 9;
    float bcol[16];
    #pragma unroll
    for (int nj = 0; nj < 8; ++nj) {
        const int col = nBlk + wn + 8 * nj + 2 * (lane & 3);
        const int bc = e * HID_DIM + (col & (HID_DIM - 1));
        bcol[2*nj]   = bias[bc];
        bcol[2*nj+1] = bias[bc + 1];
    }
    #pragma unroll
    for (int mi = 0; mi < 4; ++mi)
        #pragma unroll
        for (int h = 0; h < 2; ++h) {
            const int row = mBlk + wm + 16 * mi + (lane >> 2) + 8 * h;
            const float g = gate[(size_t)row * N_EXP + e];
            #pragma unroll
            for (int nj = 0; nj < 8; ++nj) {
                const int col = nBlk + wn + 8 * nj + 2 * (lane & 3);
                float v0 = fmaxf(acc[mi][nj][2*h]   + bcol[2*nj],   0.f) * g;
                float v1 = fmaxf(acc[mi][nj][2*h+1] + bcol[2*nj+1], 0.f) * g;
                *reinterpret_cast<uint32_t*>(Chs + (size_t)row * H3 + col) = pk_h2(v0, v1);
            }
        }
}

// ======= GEMM2 (R11 config): CTA 128x128, 8 warps (2Mx4N), warp 64x32 =======
// 256 threads, BK=32, 5-stage pipeline (16KB/stage; 80KB/CTA, 2 CTAs/SM).
// Measured best for K=3072.
#define G2_BM 128
#define G2_BN 128
#define G2_BK 32
#define G2_STAGES 5
#define G2_STAGE_BYTES 16384
#define G2_SMEM (G2_STAGES * G2_STAGE_BYTES)

__global__ __launch_bounds__(256, 2) void gemm2_mma(
    const __half* __restrict__ A, const __half* __restrict__ Bw,
    const float* __restrict__ bias, const float* __restrict__ gate,
    float* __restrict__ Cf)
{
    extern __shared__ char smem[];
    const uint32_t sbase = smem_u32(smem);
    const int tid  = threadIdx.x;
    const int wid  = tid >> 5;
    const int lane = tid & 31;
    const int mBlk = blockIdx.y * G2_BM;
    const int nBlk = blockIdx.x * G2_BN;
    const int wm = (wid >> 2) * 64;
    const int wn = (wid & 3) * 32;
    constexpr int K = H3;
    constexpr int NK = K / G2_BK;

    const __half* srcTab[2];
    srcTab[0] = A  + (size_t)mBlk * K;
    srcTab[1] = Bw + (size_t)nBlk * K;

    float acc[4][4][4];
    #pragma unroll
    for (int i = 0; i < 4; ++i)
        #pragma unroll
        for (int j = 0; j < 4; ++j)
            #pragma unroll
            for (int q = 0; q < 4; ++q) acc[i][j][q] = 0.f;

    auto load_stage = [&](int s) {
        const int k0 = s * G2_BK;
        const uint32_t sb = sbase + (s % G2_STAGES) * G2_STAGE_BYTES;
        #pragma unroll
        for (int j = 0; j < 4; ++j) {
            int idx = tid + j * 256;          // 0..1023
            int reg = idx >> 9;               // 0=A, 1=B
            int i = idx & 511;
            int row = i >> 2, c = i & 3;
            cp16(sb + reg * 8192 + sw_off(row, c),
                 srcTab[reg] + (size_t)row * K + k0 + c * 8);
        }
        cp_commit();
    };

    #pragma unroll
    for (int s = 0; s < G2_STAGES - 1; ++s) load_stage(s);

    const int rA = wm + (lane & 15);
    const int rB = wn + ((lane >> 4) << 3) + (lane & 7);
    const int cAoff = lane >> 4;
    const int cBoff = (lane >> 3) & 1;

    #pragma unroll 5
    for (int s = 0; s < NK; ++s) {
        cp_wait<G2_STAGES - 2>();
        __syncthreads();
        const uint32_t sb = sbase + (s % G2_STAGES) * G2_STAGE_BYTES;

        uint32_t Ah[4][4], Bh[4][2];
        #pragma unroll
        for (int mi = 0; mi < 4; ++mi)
            ldsm4(Ah[mi], sb + sw_off(rA + 16 * mi, cAoff));
        #pragma unroll
        for (int jp = 0; jp < 2; ++jp) {
            uint32_t t[4];
            ldsm4(t, sb + 8192 + sw_off(rB + 16 * jp, cBoff));
            Bh[2*jp][0] = t[0]; Bh[2*jp][1] = t[1];
            Bh[2*jp+1][0] = t[2]; Bh[2*jp+1][1] = t[3];
        }

        if (s + G2_STAGES - 1 < NK) load_stage(s + G2_STAGES - 1);
        else cp_commit();

        #pragma unroll
        for (int kk = 0; kk < 2; ++kk) {
            uint32_t An[4][4], Bn[4][2];
            if (kk == 0) {   // prefetch kk1 fragments under kk0 MMAs
                #pragma unroll
                for (int mi = 0; mi < 4; ++mi)
                    ldsm4(An[mi], sb + sw_off(rA + 16 * mi, 2 + cAoff));
                #pragma unroll
                for (int jp = 0; jp < 2; ++jp) {
                    uint32_t t[4];
                    ldsm4(t, sb + 8192 + sw_off(rB + 16 * jp, 2 + cBoff));
                    Bn[2*jp][0] = t[0]; Bn[2*jp][1] = t[1];
                    Bn[2*jp+1][0] = t[2]; Bn[2*jp+1][1] = t[3];
                }
            }
            #pragma unroll
            for (int mi = 0; mi < 4; ++mi)
                #pragma unroll
                for (int nj = 0; nj < 4; ++nj)
                    mma_f16(acc[mi][nj], Ah[mi], Bh[nj]);
            if (kk == 0) {
                #pragma unroll
                for (int mi = 0; mi < 4; ++mi)
                    #pragma unroll
                    for (int q = 0; q < 4; ++q) Ah[mi][q] = An[mi][q];
                #pragma unroll
                for (int nj = 0; nj < 4; ++nj) {
                    Bh[nj][0] = Bn[nj][0]; Bh[nj][1] = Bn[nj][1];
                }
            }
        }
    }

    // epilogue: out = acc + gate @ b2
    float bb[8][N_EXP];
    #pragma unroll
    for (int nj = 0; nj < 4; ++nj) {
        const int col = nBlk + wn + 8 * nj + 2 * (lane & 3);
        #pragma unroll
        for (int q = 0; q < N_EXP; ++q) {
            bb[2*nj][q]   = bias[q * OUT_DIM + col];
            bb[2*nj+1][q] = bias[q * OUT_DIM + col + 1];
        }
    }
    #pragma unroll
    for (int mi = 0; mi < 4; ++mi)
        #pragma unroll
        for (int h = 0; h < 2; ++h) {
            const int row = mBlk + wm + 16 * mi + (lane >> 2) + 8 * h;
            const float2* gp = reinterpret_cast<const float2*>(gate + (size_t)row * N_EXP);
            float2 gA = gp[0], gB = gp[1], gC = gp[2];
            float gw[N_EXP] = {gA.x, gA.y, gB.x, gB.y, gC.x, gC.y};
            #pragma unroll
            for (int nj = 0; nj < 4; ++nj) {
                const int col = nBlk + wn + 8 * nj + 2 * (lane & 3);
                float v0 = acc[mi][nj][2*h];
                float v1 = acc[mi][nj][2*h+1];
                #pragma unroll
                for (int q = 0; q < N_EXP; ++q) {
                    v0 = fmaf(gw[q], bb[2*nj][q],   v0);
                    v1 = fmaf(gw[q], bb[2*nj+1][q], v1);
                }
                *reinterpret_cast<float2*>(Cf + (size_t)row * OUT_DIM + col) = make_float2(v0, v1);
            }
        }
}

// ---------------------------------------------------------------------------
extern "C" void kernel_launch(void* const* d_in, const int* in_sizes, int n_in,
                              void* d_out, int out_size)
{
    const float* x   = (const float*)d_in[0];
    const float* g2w = (const float*)d_in[1];
    const float* g2b = (const float*)d_in[2];
    const float* g3w = (const float*)d_in[3];
    const float* g3b = (const float*)d_in[4];
    const float* w1  = (const float*)d_in[5];
    const float* b1  = (const float*)d_in[6];
    const float* w2  = (const float*)d_in[7];
    const float* b2  = (const float*)d_in[8];
    float* out = (float*)d_out;

    const int B = in_sizes[0] / IN_DIM;   // 32768

    float* gate;
    __half *xh, *w1q, *w2q, *hs;
    cudaGetSymbolAddress((void**)&gate, g_gate);
    cudaGetSymbolAddress((void**)&xh, g_xh);
    cudaGetSymbolAddress((void**)&w1q, g_w1);
    cudaGetSymbolAddress((void**)&w2q, g_w2);
    cudaGetSymbolAddress((void**)&hs, g_hs);

    cudaFuncSetAttribute(gemm1_mma, cudaFuncAttributeMaxDynamicSharedMemorySize, G1_SMEM);
    cudaFuncSetAttribute(gemm2_mma, cudaFuncAttributeMaxDynamicSharedMemorySize, G2_SMEM);

    // 1) gate + fp16 quantize x
    gate_split_kernel<<<(B + 7) / 8, 256>>>(x, g2w, g2b, g3w, g3b, gate, xh, B);

    // 2) transpose + fp16 quantize weights
    transquant_kernel<<<dim3(HID_DIM/32, IN_DIM/32, N_EXP), dim3(32, 8)>>>(w1, w1q, IN_DIM, HID_DIM);
    transquant_kernel<<<dim3(OUT_DIM/32, H3/32, 1),        dim3(32, 8)>>>(w2, w2q, H3, OUT_DIM);

    // 3) hs = fp16(relu(x @ W1 + b1) * gate)   [B,3072]  (R15-best GEMM1)
    gemm1_mma<<<dim3(H3/G1_BN, B/G1_BM), 128, G1_SMEM>>>(
        xh, w1q, b1, gate, hs);

    // 4) out = hs @ W2 + gate @ b2             [B,1024]  (R11-best GEMM2)
    gemm2_mma<<<dim3(OUT_DIM/G2_BN, B/G2_BM), 256, G2_SMEM>>>(
        hs, w2q, b2, gate, out);
}